// round 14
// baseline (speedup 1.0000x reference)
#include <cuda_runtime.h>
#include <cuda_fp16.h>
#include <cstdint>

#define B_SZ 8192
#define L_SZ 64
#define EMB  64
#define HID  128
#define G3   384
#define OUTD 128
#define NVAL 1000

__device__ float g_tab[NVAL * G3];      // xg table, PERMUTED within 16-chunks (fp32, L2-hot)
__device__ float g_Wih_t[EMB * G3];
__device__ float g_cbias[G3];
__device__ uint32_t g_Bf[8 * 8 * 32 * 12];  // Whh fp16 B-fragments, 96KB
__device__ uint32_t g_Of[8 * 32 * 32];      // Wout fp16 B-fragments (read from L2)

__device__ __forceinline__ float ftanh_fast(float x) {
    float r;
    asm("tanh.approx.f32 %0, %1;" : "=f"(r) : "f"(x));
    return r;
}
__device__ __forceinline__ float fsig_fast(float x) {
    return fmaf(0.5f, ftanh_fast(0.5f * x), 0.5f);
}
__device__ __forceinline__ uint32_t packh2(float lo, float hi) {
    __half2 h = __floats2half2_rn(lo, hi);
    return *reinterpret_cast<uint32_t*>(&h);
}
__device__ __forceinline__ void hmma(float* d, const uint32_t* a, uint32_t b0, uint32_t b1) {
    asm volatile("mma.sync.aligned.m16n8k16.row.col.f32.f16.f16.f32 "
        "{%0,%1,%2,%3}, {%4,%5,%6,%7}, {%8,%9}, {%0,%1,%2,%3};"
        : "+f"(d[0]), "+f"(d[1]), "+f"(d[2]), "+f"(d[3])
        : "r"(a[0]), "r"(a[1]), "r"(a[2]), "r"(a[3]), "r"(b0), "r"(b1));
}
__device__ __forceinline__ int pperm(int o) {
    return 4 * ((o & 7) >> 1) + (((o >> 3) & 1) << 1) + (o & 1);
}

// ---------------- prep: fragment images (unchanged layouts) ----------------
__global__ void prep_kernel(const float* __restrict__ Wih, const float* __restrict__ Whh,
                            const float* __restrict__ bih, const float* __restrict__ bhh,
                            const float* __restrict__ Wout) {
    int i = blockIdx.x * blockDim.x + threadIdx.x;
    if (i < EMB * G3) { int k = i / G3, gj = i % G3; g_Wih_t[i] = Wih[gj * EMB + k]; }
    if (i < G3) g_cbias[i] = bih[i] + (i < 2 * HID ? bhh[i] : 0.0f);
    if (i < G3 * HID) {
        int gj = i / HID, k = i % HID;
        uint16_t hb = __half_as_ushort(__float2half_rn(Whh[i]));
        int gate = gj >> 7, jr = gj & 127;
        int jc = jr >> 4, nt = (jr >> 3) & 1, nl = jr & 7;
        int kc = k >> 4, kk = k & 15;
        int breg = kk >> 3, q = (kk & 7) >> 1, hs = kk & 1;
        int T = nl * 4 + q, f = gate * 2 + nt;
        int u = ((jc * 8 + kc) * 32 + T) * 12 + f * 2 + breg;
        ((uint16_t*)g_Bf)[u * 2 + hs] = hb;
    }
    if (i < OUTD * HID) {
        int o = i / HID, k = i % HID;
        uint16_t hb = __half_as_ushort(__float2half_rn(Wout[i]));
        int f = o >> 3, nl = o & 7;
        int kc = k >> 4, kk = k & 15;
        int breg = kk >> 3, q = (kk & 7) >> 1, hs = kk & 1;
        int T = nl * 4 + q;
        int u = (kc * 32 + T) * 32 + f * 2 + breg;
        ((uint16_t*)g_Of)[u * 2 + hs] = hb;
    }
}

__global__ void table_kernel(const float* __restrict__ embed) {
    __shared__ float es[EMB];
    const int v = blockIdx.x, gj = threadIdx.x;
    if (gj < EMB) es[gj] = embed[v * EMB + gj];
    __syncthreads();
    float acc = 0.0f;
    #pragma unroll 8
    for (int k = 0; k < EMB; k++) acc = fmaf(es[k], g_Wih_t[k * G3 + gj], acc);
    const int gate = gj >> 7, rest = gj & 127, chunk = rest >> 4, o = rest & 15;
    g_tab[v * G3 + gate * 128 + chunk * 16 + pperm(o)] = acc + g_cbias[gj];
}

// ---- GRU: 2 M-tiles per warp (B-fragment reuse), 4-way j-split quads, 2 warps/SMSP ----
#define NTH 256
#define EXCH_U32 24704                        // after Bs(24576) + bns(128)
#define GRU_SMEM ((EXCH_U32 + 8192) * 4)      // 131584 bytes
__global__ __launch_bounds__(NTH, 1) void gru_kernel(const int* __restrict__ x,
                                                     const float* __restrict__ bhh,
                                                     const float* __restrict__ bout,
                                                     float* __restrict__ out) {
    extern __shared__ uint32_t sm[];
    uint32_t* Bs = sm;                        // 24576 u32 (96KB)
    float* bns = (float*)(sm + 24576);        // 128 floats, permuted bhh_n
    uint4* exch = (uint4*)(sm + EXCH_U32);    // [parity][tile][warp8][lane][slot2]
    const int tid = threadIdx.x;
    {
        uint4* d = (uint4*)sm;
        const uint4* s1 = (const uint4*)g_Bf;
        for (int i = tid; i < 6144; i += NTH) d[i] = s1[i];
    }
    if (tid < 128) {
        int o = tid & 15, chunk = tid >> 4;
        bns[chunk * 16 + pperm(o)] = bhh[256 + tid];
    }
    __syncthreads();

    const int w = tid >> 5, T = tid & 31;
    const int sub = w & 3, quad = w >> 2;     // quad (4 warps) shares 32 rows; sub splits j 4-way
    const int g = T >> 2, a4 = (T & 3) * 4;
    const int row0 = blockIdx.x * 64 + quad * 32 + g;   // tile0 rowA; +8 rowB; +16/+24 tile1
    const int jbase = sub * 32;
    const float* __restrict__ tab = g_tab;
    const float* bnsw = bns + jbase + a4;
    const uint32_t* Bsw = Bs + sub * 2 * 8 * 32 * 12;

    uint32_t A0[32], A1[32];
    float hp0[16], hp1[16];
    #pragma unroll
    for (int i = 0; i < 32; i++) { A0[i] = 0u; A1[i] = 0u; }
    #pragma unroll
    for (int i = 0; i < 16; i++) { hp0[i] = 0.0f; hp1[i] = 0.0f; }

    int iA0 = x[(row0) * L_SZ],      iB0 = x[(row0 + 8) * L_SZ];
    int iA1 = x[(row0 + 16) * L_SZ], iB1 = x[(row0 + 24) * L_SZ];

    #pragma unroll 1
    for (int t = 0; t < L_SZ; t++) {
        int jA0 = iA0, jB0 = iB0, jA1 = iA1, jB1 = iB1;
        if (t + 1 < L_SZ) {
            jA0 = x[(row0) * L_SZ + t + 1];      jB0 = x[(row0 + 8) * L_SZ + t + 1];
            jA1 = x[(row0 + 16) * L_SZ + t + 1]; jB1 = x[(row0 + 24) * L_SZ + t + 1];
        }
        uint4 An0[2], An1[2];
        #pragma unroll
        for (int jci = 0; jci < 2; jci++) {
            const int jo = jci * 16;
            const float* pA0 = tab + (size_t)iA0 * G3 + jbase + a4 + jo;
            const float* pB0 = tab + (size_t)iB0 * G3 + jbase + a4 + jo;
            const float* pA1 = tab + (size_t)iA1 * G3 + jbase + a4 + jo;
            const float* pB1 = tab + (size_t)iB1 * G3 + jbase + a4 + jo;
            // xg loads issue here; consumed only in the epilogue (covered by 96 HMMAs)
            float4 rA0 = __ldg((const float4*)(pA0)),       rB0 = __ldg((const float4*)(pB0));
            float4 zA0 = __ldg((const float4*)(pA0 + 128)), zB0 = __ldg((const float4*)(pB0 + 128));
            float4 nA0 = __ldg((const float4*)(pA0 + 256)), nB0 = __ldg((const float4*)(pB0 + 256));
            float4 rA1 = __ldg((const float4*)(pA1)),       rB1 = __ldg((const float4*)(pB1));
            float4 zA1 = __ldg((const float4*)(pA1 + 128)), zB1 = __ldg((const float4*)(pB1 + 128));
            float4 nA1 = __ldg((const float4*)(pA1 + 256)), nB1 = __ldg((const float4*)(pB1 + 256));
            float4 bn4 = *(const float4*)(bnsw + jo);

            float d0[6][4] = {
                {0,0,0,0}, {0,0,0,0}, {0,0,0,0}, {0,0,0,0},
                {bn4.x, bn4.y, bn4.x, bn4.y}, {bn4.z, bn4.w, bn4.z, bn4.w}
            };
            float d1[6][4] = {
                {0,0,0,0}, {0,0,0,0}, {0,0,0,0}, {0,0,0,0},
                {bn4.x, bn4.y, bn4.x, bn4.y}, {bn4.z, bn4.w, bn4.z, bn4.w}
            };

            #pragma unroll
            for (int kc = 0; kc < 8; kc++) {
                const uint4* bp = (const uint4*)(Bsw + ((jci * 8 + kc) * 32 + T) * 12);
                uint4 b0 = bp[0], b1 = bp[1], b2 = bp[2];
                hmma(d0[0], &A0[kc * 4], b0.x, b0.y);
                hmma(d0[1], &A0[kc * 4], b0.z, b0.w);
                hmma(d0[2], &A0[kc * 4], b1.x, b1.y);
                hmma(d0[3], &A0[kc * 4], b1.z, b1.w);
                hmma(d0[4], &A0[kc * 4], b2.x, b2.y);
                hmma(d0[5], &A0[kc * 4], b2.z, b2.w);
                hmma(d1[0], &A1[kc * 4], b0.x, b0.y);
                hmma(d1[1], &A1[kc * 4], b0.z, b0.w);
                hmma(d1[2], &A1[kc * 4], b1.x, b1.y);
                hmma(d1[3], &A1[kc * 4], b1.z, b1.w);
                hmma(d1[4], &A1[kc * 4], b2.x, b2.y);
                hmma(d1[5], &A1[kc * 4], b2.z, b2.w);
            }

            {   // epilogue tile0
                float xr[8] = {rA0.x, rA0.y, rB0.x, rB0.y, rA0.z, rA0.w, rB0.z, rB0.w};
                float xz[8] = {zA0.x, zA0.y, zB0.x, zB0.y, zA0.z, zA0.w, zB0.z, zB0.w};
                float xn[8] = {nA0.x, nA0.y, nB0.x, nB0.y, nA0.z, nA0.w, nB0.z, nB0.w};
                float hv[8];
                #pragma unroll
                for (int u = 0; u < 8; u++) {
                    int nt = u >> 2, pos = u & 3;
                    float r = fsig_fast(d0[nt][pos] + xr[u]);
                    float z = fsig_fast(d0[2 + nt][pos] + xz[u]);
                    float n = ftanh_fast(fmaf(r, d0[4 + nt][pos], xn[u]));
                    float h = fmaf(z, hp0[jci * 8 + u] - n, n);
                    hp0[jci * 8 + u] = h;
                    hv[u] = h;
                }
                An0[jci] = make_uint4(packh2(hv[0], hv[1]), packh2(hv[2], hv[3]),
                                      packh2(hv[4], hv[5]), packh2(hv[6], hv[7]));
            }
            {   // epilogue tile1
                float xr[8] = {rA1.x, rA1.y, rB1.x, rB1.y, rA1.z, rA1.w, rB1.z, rB1.w};
                float xz[8] = {zA1.x, zA1.y, zB1.x, zB1.y, zA1.z, zA1.w, zB1.z, zB1.w};
                float xn[8] = {nA1.x, nA1.y, nB1.x, nB1.y, nA1.z, nA1.w, nB1.z, nB1.w};
                float hv[8];
                #pragma unroll
                for (int u = 0; u < 8; u++) {
                    int nt = u >> 2, pos = u & 3;
                    float r = fsig_fast(d1[nt][pos] + xr[u]);
                    float z = fsig_fast(d1[2 + nt][pos] + xz[u]);
                    float n = ftanh_fast(fmaf(r, d1[4 + nt][pos], xn[u]));
                    float h = fmaf(z, hp1[jci * 8 + u] - n, n);
                    hp1[jci * 8 + u] = h;
                    hv[u] = h;
                }
                An1[jci] = make_uint4(packh2(hv[0], hv[1]), packh2(hv[2], hv[3]),
                                      packh2(hv[4], hv[5]), packh2(hv[6], hv[7]));
            }
        }

        // quad h-exchange (both tiles), one named barrier per quad
        {
            const int p = t & 1;
            uint4* m0 = exch + (((p * 2 + 0) * 8 + w) * 32 + T) * 2;
            m0[0] = An0[0]; m0[1] = An0[1];
            uint4* m1 = exch + (((p * 2 + 1) * 8 + w) * 32 + T) * 2;
            m1[0] = An1[0]; m1[1] = An1[1];
            asm volatile("bar.sync %0, 128;" :: "r"(1 + quad) : "memory");
            #pragma unroll
            for (int c = 0; c < 8; c++) {
                uint4 v0 = exch[(((p * 2 + 0) * 8 + quad * 4 + (c >> 1)) * 32 + T) * 2 + (c & 1)];
                A0[c * 4 + 0] = v0.x; A0[c * 4 + 1] = v0.y;
                A0[c * 4 + 2] = v0.z; A0[c * 4 + 3] = v0.w;
                uint4 v1 = exch[(((p * 2 + 1) * 8 + quad * 4 + (c >> 1)) * 32 + T) * 2 + (c & 1)];
                A1[c * 4 + 0] = v1.x; A1[c * 4 + 1] = v1.y;
                A1[c * 4 + 2] = v1.z; A1[c * 4 + 3] = v1.w;
            }
        }
        iA0 = jA0; iB0 = jB0; iA1 = jA1; iB1 = jB1;
    }

    // output projection: Wout fragments streamed from L2 (g_Of), sub covers 4 f's
    float od0[4][4], od1[4][4];
    #pragma unroll
    for (int f = 0; f < 4; f++)
        #pragma unroll
        for (int p = 0; p < 4; p++) { od0[f][p] = 0.0f; od1[f][p] = 0.0f; }
    #pragma unroll
    for (int kc = 0; kc < 8; kc++) {
        const uint4* op = ((const uint4*)(g_Of + (kc * 32 + T) * 32)) + sub * 2;
        uint4 v0 = __ldg(op), v1 = __ldg(op + 1);
        hmma(od0[0], &A0[kc * 4], v0.x, v0.y);
        hmma(od0[1], &A0[kc * 4], v0.z, v0.w);
        hmma(od0[2], &A0[kc * 4], v1.x, v1.y);
        hmma(od0[3], &A0[kc * 4], v1.z, v1.w);
        hmma(od1[0], &A1[kc * 4], v0.x, v0.y);
        hmma(od1[1], &A1[kc * 4], v0.z, v0.w);
        hmma(od1[2], &A1[kc * 4], v1.x, v1.y);
        hmma(od1[3], &A1[kc * 4], v1.z, v1.w);
    }
    const int q2 = (T & 3) * 2;
    #pragma unroll
    for (int f2 = 0; f2 < 4; f2++) {
        const int f = sub * 4 + f2;
        float2 bo = *(const float2*)(bout + f * 8 + q2);
        *(float2*)(out + (size_t)(row0) * OUTD + f * 8 + q2) =
            make_float2(od0[f2][0] + bo.x, od0[f2][1] + bo.y);
        *(float2*)(out + (size_t)(row0 + 8) * OUTD + f * 8 + q2) =
            make_float2(od0[f2][2] + bo.x, od0[f2][3] + bo.y);
        *(float2*)(out + (size_t)(row0 + 16) * OUTD + f * 8 + q2) =
            make_float2(od1[f2][0] + bo.x, od1[f2][1] + bo.y);
        *(float2*)(out + (size_t)(row0 + 24) * OUTD + f * 8 + q2) =
            make_float2(od1[f2][2] + bo.x, od1[f2][3] + bo.y);
    }
}

extern "C" void kernel_launch(void* const* d_in, const int* in_sizes, int n_in,
                              void* d_out, int out_size) {
    const int*   x     = (const int*)d_in[0];
    const float* embed = (const float*)d_in[1];
    const float* Wih   = (const float*)d_in[2];
    const float* Whh   = (const float*)d_in[3];
    const float* bih   = (const float*)d_in[4];
    const float* bhh   = (const float*)d_in[5];
    const float* Wout  = (const float*)d_in[6];
    const float* bout  = (const float*)d_in[7];
    float* out = (float*)d_out;

    static bool attr_done = false;
    if (!attr_done) {
        cudaFuncSetAttribute(gru_kernel, cudaFuncAttributeMaxDynamicSharedMemorySize, GRU_SMEM);
        attr_done = true;
    }

    prep_kernel<<<192, 256>>>(Wih, Whh, bih, bhh, Wout);
    table_kernel<<<NVAL, G3>>>(embed);
    gru_kernel<<<B_SZ / 64, NTH, GRU_SMEM>>>(x, bhh, bout, out);
}

// round 15
// speedup vs baseline: 1.0270x; 1.0270x over previous
#include <cuda_runtime.h>
#include <cuda_fp16.h>
#include <cstdint>

#define B_SZ 8192
#define L_SZ 64
#define EMB  64
#define HID  128
#define G3   384
#define OUTD 128
#define NVAL 1000

__device__ float g_tab[NVAL * G3];      // xg table, PERMUTED within 16-chunks (fp32, L2-hot)
__device__ float g_Wih_t[EMB * G3];
__device__ float g_cbias[G3];
__device__ uint32_t g_Bf[8 * 8 * 32 * 12];  // Whh fp16 B-fragments, 96KB
__device__ uint32_t g_Of[8 * 32 * 32];      // Wout fp16 B-fragments, 32KB

__device__ __forceinline__ float ftanh_fast(float x) {
    float r;
    asm("tanh.approx.f32 %0, %1;" : "=f"(r) : "f"(x));
    return r;
}
__device__ __forceinline__ float fsig_fast(float x) {
    return fmaf(0.5f, ftanh_fast(0.5f * x), 0.5f);
}
__device__ __forceinline__ uint32_t packh2(float lo, float hi) {
    __half2 h = __floats2half2_rn(lo, hi);
    return *reinterpret_cast<uint32_t*>(&h);
}
// fp32-accum HMMA (output projection only)
__device__ __forceinline__ void hmma(float* d, const uint32_t* a, uint32_t b0, uint32_t b1) {
    asm volatile("mma.sync.aligned.m16n8k16.row.col.f32.f16.f16.f32 "
        "{%0,%1,%2,%3}, {%4,%5,%6,%7}, {%8,%9}, {%0,%1,%2,%3};"
        : "+f"(d[0]), "+f"(d[1]), "+f"(d[2]), "+f"(d[3])
        : "r"(a[0]), "r"(a[1]), "r"(a[2]), "r"(a[3]), "r"(b0), "r"(b1));
}
// fp16-accum HMMA (GRU mainloop) — D is 2 regs of f16x2
__device__ __forceinline__ void hmma16(uint32_t* d, const uint32_t* a, uint32_t b0, uint32_t b1) {
    asm volatile("mma.sync.aligned.m16n8k16.row.col.f16.f16.f16.f16 "
        "{%0,%1}, {%2,%3,%4,%5}, {%6,%7}, {%0,%1};"
        : "+r"(d[0]), "+r"(d[1])
        : "r"(a[0]), "r"(a[1]), "r"(a[2]), "r"(a[3]), "r"(b0), "r"(b1));
}
__device__ __forceinline__ int pperm(int o) {
    return 4 * ((o & 7) >> 1) + (((o >> 3) & 1) << 1) + (o & 1);
}

// ---------------- prep: fragment images ----------------
__global__ void prep_kernel(const float* __restrict__ Wih, const float* __restrict__ Whh,
                            const float* __restrict__ bih, const float* __restrict__ bhh,
                            const float* __restrict__ Wout) {
    int i = blockIdx.x * blockDim.x + threadIdx.x;
    if (i < EMB * G3) { int k = i / G3, gj = i % G3; g_Wih_t[i] = Wih[gj * EMB + k]; }
    if (i < G3) g_cbias[i] = bih[i] + (i < 2 * HID ? bhh[i] : 0.0f);
    if (i < G3 * HID) {
        int gj = i / HID, k = i % HID;
        uint16_t hb = __half_as_ushort(__float2half_rn(Whh[i]));
        int gate = gj >> 7, jr = gj & 127;
        int jc = jr >> 4, nt = (jr >> 3) & 1, nl = jr & 7;
        int kc = k >> 4, kk = k & 15;
        int breg = kk >> 3, q = (kk & 7) >> 1, hs = kk & 1;
        int T = nl * 4 + q, f = gate * 2 + nt;
        int u = ((jc * 8 + kc) * 32 + T) * 12 + f * 2 + breg;
        ((uint16_t*)g_Bf)[u * 2 + hs] = hb;
    }
    if (i < OUTD * HID) {
        int o = i / HID, k = i % HID;
        uint16_t hb = __half_as_ushort(__float2half_rn(Wout[i]));
        int f = o >> 3, nl = o & 7;
        int kc = k >> 4, kk = k & 15;
        int breg = kk >> 3, q = (kk & 7) >> 1, hs = kk & 1;
        int T = nl * 4 + q;
        int u = (kc * 32 + T) * 32 + f * 2 + breg;
        ((uint16_t*)g_Of)[u * 2 + hs] = hb;
    }
}

__global__ void table_kernel(const float* __restrict__ embed) {
    __shared__ float es[EMB];
    const int v = blockIdx.x, gj = threadIdx.x;
    if (gj < EMB) es[gj] = embed[v * EMB + gj];
    __syncthreads();
    float acc = 0.0f;
    #pragma unroll 8
    for (int k = 0; k < EMB; k++) acc = fmaf(es[k], g_Wih_t[k * G3 + gj], acc);
    const int gate = gj >> 7, rest = gj & 127, chunk = rest >> 4, o = rest & 15;
    g_tab[v * G3 + gate * 128 + chunk * 16 + pperm(o)] = acc + g_cbias[gj];
}

// ---- GRU: fp16-accum HMMA (2 split chains + fp32 combine), pair N-split, 2 warps/SMSP ----
#define NTH 256
#define EXCH_U32 32896
#define GRU_SMEM ((EXCH_U32 + 2 * NTH * 16) * 4)   // 164352 bytes
__global__ __launch_bounds__(NTH, 1) void gru_kernel(const int* __restrict__ x,
                                                     const float* __restrict__ bhh,
                                                     const float* __restrict__ bout,
                                                     float* __restrict__ out) {
    extern __shared__ uint32_t sm[];
    uint32_t* Bs = sm;                      // 24576 u32 (96KB)
    uint32_t* Os = sm + 24576;              // 8192 u32 (32KB)
    float* bns = (float*)(sm + 32768);      // 128 floats, permuted bhh_n
    uint4* exch = (uint4*)(sm + EXCH_U32);  // 2 x 256 threads x 4 uint4
    const int tid = threadIdx.x;
    {
        uint4* d = (uint4*)sm;
        const uint4* s1 = (const uint4*)g_Bf;
        for (int i = tid; i < 6144; i += NTH) d[i] = s1[i];
        const uint4* s2 = (const uint4*)g_Of;
        for (int i = tid; i < 2048; i += NTH) d[6144 + i] = s2[i];
    }
    if (tid < 128) {
        int o = tid & 15, chunk = tid >> 4;
        bns[chunk * 16 + pperm(o)] = bhh[256 + tid];
    }
    __syncthreads();

    const int w = tid >> 5, T = tid & 31;
    const int sub = w & 1, pairid = w >> 1;       // pair shares a 16-row tile; sub splits j
    const int g = T >> 2, a4 = (T & 3) * 4;
    const int rowA = blockIdx.x * 64 + pairid * 16 + g;
    const int rowB = rowA + 8;
    const int jbase = sub * 64;                    // own j range: [jbase, jbase+64)
    const float* __restrict__ tab = g_tab;
    const float* bnsw = bns + jbase + a4;
    const uint32_t* Bsw = Bs + sub * 4 * 8 * 32 * 12;

    uint32_t A[32];
    float hp[32];
    #pragma unroll
    for (int i = 0; i < 32; i++) A[i] = 0u;
    #pragma unroll
    for (int i = 0; i < 32; i++) hp[i] = 0.0f;

    int idxA = x[rowA * L_SZ], idxB = x[rowB * L_SZ];
    const float* tA = tab + (size_t)idxA * G3 + jbase + a4;
    const float* tB = tab + (size_t)idxB * G3 + jbase + a4;

    float4 crA = __ldg((const float4*)(tA));
    float4 crB = __ldg((const float4*)(tB));
    float4 czA = __ldg((const float4*)(tA + 128));
    float4 czB = __ldg((const float4*)(tB + 128));
    float4 cnA = __ldg((const float4*)(tA + 256));
    float4 cnB = __ldg((const float4*)(tB + 256));

    #pragma unroll 1
    for (int t = 0; t < L_SZ; t++) {
        int idxA2 = idxA, idxB2 = idxB;
        if (t + 1 < L_SZ) {
            idxA2 = x[rowA * L_SZ + t + 1];
            idxB2 = x[rowB * L_SZ + t + 1];
        }
        uint4 AnR[4];
        #pragma unroll
        for (int jci = 0; jci < 4; jci++) {
            // save this chunk's xg before prefetch overwrites
            float4 xrc_A = crA, xrc_B = crB;
            float4 xzc_A = czA, xzc_B = czB;
            float4 xnc_A = cnA, xnc_B = cnB;
            float4 bn4 = *(const float4*)(bnsw + jci * 16);

            // prefetch next own chunk (wraps into next step)
            if (jci < 3) {
                const int jn = (jci + 1) * 16;
                crA = __ldg((const float4*)(tA + jn));
                crB = __ldg((const float4*)(tB + jn));
                czA = __ldg((const float4*)(tA + 128 + jn));
                czB = __ldg((const float4*)(tB + 128 + jn));
                cnA = __ldg((const float4*)(tA + 256 + jn));
                cnB = __ldg((const float4*)(tB + 256 + jn));
            } else {
                tA = tab + (size_t)idxA2 * G3 + jbase + a4;
                tB = tab + (size_t)idxB2 * G3 + jbase + a4;
                crA = __ldg((const float4*)(tA));
                crB = __ldg((const float4*)(tB));
                czA = __ldg((const float4*)(tA + 128));
                czB = __ldg((const float4*)(tB + 128));
                cnA = __ldg((const float4*)(tA + 256));
                cnB = __ldg((const float4*)(tB + 256));
            }

            // two fp16 accumulation chains (kc 0-3, kc 4-7), combined in fp32 below
            uint32_t dA[6][2], dB[6][2];
            #pragma unroll
            for (int f = 0; f < 6; f++) {
                dA[f][0] = 0u; dA[f][1] = 0u;
                dB[f][0] = 0u; dB[f][1] = 0u;
            }
            #pragma unroll
            for (int kc = 0; kc < 4; kc++) {
                const uint4* bp = (const uint4*)(Bsw + ((jci * 8 + kc) * 32 + T) * 12);
                uint4 b0 = bp[0], b1 = bp[1], b2 = bp[2];
                hmma16(dA[0], &A[kc * 4], b0.x, b0.y);
                hmma16(dA[1], &A[kc * 4], b0.z, b0.w);
                hmma16(dA[2], &A[kc * 4], b1.x, b1.y);
                hmma16(dA[3], &A[kc * 4], b1.z, b1.w);
                hmma16(dA[4], &A[kc * 4], b2.x, b2.y);
                hmma16(dA[5], &A[kc * 4], b2.z, b2.w);
            }
            #pragma unroll
            for (int kc = 4; kc < 8; kc++) {
                const uint4* bp = (const uint4*)(Bsw + ((jci * 8 + kc) * 32 + T) * 12);
                uint4 b0 = bp[0], b1 = bp[1], b2 = bp[2];
                hmma16(dB[0], &A[kc * 4], b0.x, b0.y);
                hmma16(dB[1], &A[kc * 4], b0.z, b0.w);
                hmma16(dB[2], &A[kc * 4], b1.x, b1.y);
                hmma16(dB[3], &A[kc * 4], b1.z, b1.w);
                hmma16(dB[4], &A[kc * 4], b2.x, b2.y);
                hmma16(dB[5], &A[kc * 4], b2.z, b2.w);
            }

            // fp32 combine of the two chains
            float fv[6][4];
            #pragma unroll
            for (int f = 0; f < 6; f++) {
                float2 aLo = __half22float2(*reinterpret_cast<__half2*>(&dA[f][0]));
                float2 aHi = __half22float2(*reinterpret_cast<__half2*>(&dA[f][1]));
                float2 bLo = __half22float2(*reinterpret_cast<__half2*>(&dB[f][0]));
                float2 bHi = __half22float2(*reinterpret_cast<__half2*>(&dB[f][1]));
                fv[f][0] = aLo.x + bLo.x;
                fv[f][1] = aLo.y + bLo.y;
                fv[f][2] = aHi.x + bHi.x;
                fv[f][3] = aHi.y + bHi.y;
            }

            float xr[8] = {xrc_A.x, xrc_A.y, xrc_B.x, xrc_B.y, xrc_A.z, xrc_A.w, xrc_B.z, xrc_B.w};
            float xz[8] = {xzc_A.x, xzc_A.y, xzc_B.x, xzc_B.y, xzc_A.z, xzc_A.w, xzc_B.z, xzc_B.w};
            float xn[8] = {xnc_A.x, xnc_A.y, xnc_B.x, xnc_B.y, xnc_A.z, xnc_A.w, xnc_B.z, xnc_B.w};
            float bn[8] = {bn4.x, bn4.y, bn4.x, bn4.y, bn4.z, bn4.w, bn4.z, bn4.w};
            float hv[8];
            #pragma unroll
            for (int u = 0; u < 8; u++) {
                int nt = u >> 2, pos = u & 3;
                float r = fsig_fast(fv[nt][pos] + xr[u]);
                float z = fsig_fast(fv[2 + nt][pos] + xz[u]);
                float n = ftanh_fast(fmaf(r, fv[4 + nt][pos] + bn[u], xn[u]));
                float h = fmaf(z, hp[jci * 8 + u] - n, n);
                hp[jci * 8 + u] = h;
                hv[u] = h;
            }
            AnR[jci] = make_uint4(packh2(hv[0], hv[1]), packh2(hv[2], hv[3]),
                                  packh2(hv[4], hv[5]), packh2(hv[6], hv[7]));
        }

        // pair h-exchange: write own 4 fragments, named barrier, read partner's 4
        {
            uint4* mine = exch + ((size_t)(t & 1) * NTH + tid) * 4;
            mine[0] = AnR[0]; mine[1] = AnR[1]; mine[2] = AnR[2]; mine[3] = AnR[3];
            asm volatile("bar.sync %0, 64;" :: "r"(1 + pairid) : "memory");
            const uint4* theirs = exch + ((size_t)(t & 1) * NTH + (tid ^ 32)) * 4;
            uint4 p0 = theirs[0], p1 = theirs[1], p2 = theirs[2], p3 = theirs[3];
            if (sub == 0) {
                A[0]  = AnR[0].x; A[1]  = AnR[0].y; A[2]  = AnR[0].z; A[3]  = AnR[0].w;
                A[4]  = AnR[1].x; A[5]  = AnR[1].y; A[6]  = AnR[1].z; A[7]  = AnR[1].w;
                A[8]  = AnR[2].x; A[9]  = AnR[2].y; A[10] = AnR[2].z; A[11] = AnR[2].w;
                A[12] = AnR[3].x; A[13] = AnR[3].y; A[14] = AnR[3].z; A[15] = AnR[3].w;
                A[16] = p0.x; A[17] = p0.y; A[18] = p0.z; A[19] = p0.w;
                A[20] = p1.x; A[21] = p1.y; A[22] = p1.z; A[23] = p1.w;
                A[24] = p2.x; A[25] = p2.y; A[26] = p2.z; A[27] = p2.w;
                A[28] = p3.x; A[29] = p3.y; A[30] = p3.z; A[31] = p3.w;
            } else {
                A[0]  = p0.x; A[1]  = p0.y; A[2]  = p0.z; A[3]  = p0.w;
                A[4]  = p1.x; A[5]  = p1.y; A[6]  = p1.z; A[7]  = p1.w;
                A[8]  = p2.x; A[9]  = p2.y; A[10] = p2.z; A[11] = p2.w;
                A[12] = p3.x; A[13] = p3.y; A[14] = p3.z; A[15] = p3.w;
                A[16] = AnR[0].x; A[17] = AnR[0].y; A[18] = AnR[0].z; A[19] = AnR[0].w;
                A[20] = AnR[1].x; A[21] = AnR[1].y; A[22] = AnR[1].z; A[23] = AnR[1].w;
                A[24] = AnR[2].x; A[25] = AnR[2].y; A[26] = AnR[2].z; A[27] = AnR[2].w;
                A[28] = AnR[3].x; A[29] = AnR[3].y; A[30] = AnR[3].z; A[31] = AnR[3].w;
            }
        }
        idxA = idxA2; idxB = idxB2;
    }

    // output projection (fp32 accum, split: sub covers 8 of 16 f-pairs)
    float od[8][4];
    #pragma unroll
    for (int f = 0; f < 8; f++)
        #pragma unroll
        for (int p = 0; p < 4; p++) od[f][p] = 0.0f;
    #pragma unroll
    for (int kc = 0; kc < 8; kc++) {
        const uint4* op = (const uint4*)(Os + (kc * 32 + T) * 32) + sub * 4;
        #pragma unroll
        for (int f2 = 0; f2 < 4; f2++) {
            uint4 v = op[f2];
            hmma(od[f2 * 2 + 0], &A[kc * 4], v.x, v.y);
            hmma(od[f2 * 2 + 1], &A[kc * 4], v.z, v.w);
        }
    }
    const int q2 = (T & 3) * 2;
    #pragma unroll
    for (int f2 = 0; f2 < 8; f2++) {
        const int f = sub * 8 + f2;
        float2 bo = *(const float2*)(bout + f * 8 + q2);
        float2 oA = make_float2(od[f2][0] + bo.x, od[f2][1] + bo.y);
        float2 oB = make_float2(od[f2][2] + bo.x, od[f2][3] + bo.y);
        *(float2*)(out + (size_t)rowA * OUTD + f * 8 + q2) = oA;
        *(float2*)(out + (size_t)rowB * OUTD + f * 8 + q2) = oB;
    }
}

extern "C" void kernel_launch(void* const* d_in, const int* in_sizes, int n_in,
                              void* d_out, int out_size) {
    const int*   x     = (const int*)d_in[0];
    const float* embed = (const float*)d_in[1];
    const float* Wih   = (const float*)d_in[2];
    const float* Whh   = (const float*)d_in[3];
    const float* bih   = (const float*)d_in[4];
    const float* bhh   = (const float*)d_in[5];
    const float* Wout  = (const float*)d_in[6];
    const float* bout  = (const float*)d_in[7];
    float* out = (float*)d_out;

    static bool attr_done = false;
    if (!attr_done) {
        cudaFuncSetAttribute(gru_kernel, cudaFuncAttributeMaxDynamicSharedMemorySize, GRU_SMEM);
        attr_done = true;
    }

    prep_kernel<<<192, 256>>>(Wih, Whh, bih, bhh, Wout);
    table_kernel<<<NVAL, G3>>>(embed);
    gru_kernel<<<B_SZ / 64, NTH, GRU_SMEM>>>(x, bhh, bout, out);
}